// round 3
// baseline (speedup 1.0000x reference)
#include <cuda_runtime.h>
#include <cuda_bf16.h>
#include <cstdint>

#define N_SEQ 512
#define D_IN 64
#define D_HID 128
#define LN_EPS 1e-5f
constexpr size_t R_TOT = (size_t)N_SEQ * N_SEQ;   // 262144

// ---------------- scratch (static device globals — allocation-free) ----------
__device__ float g_a[(size_t)D_HID * R_TOT];     // [c][i*N+k]  tf32-rounded
__device__ float g_b[(size_t)D_HID * R_TOT];     // [c][j*N+k]  tf32-rounded
__device__ float g_gate[R_TOT * D_IN];           // [row][64]   post-sigmoid fp32
__device__ float g_op[(size_t)D_HID * R_TOT];    // [c][i*N+j]  fp32

// ---------------- helpers ----------------------------------------------------
__device__ __forceinline__ float tf32f(float x){
    uint32_t u = __float_as_uint(x);
    asm("cvt.rna.tf32.f32 %0, %0;" : "+r"(u));
    return __uint_as_float(u);
}
__device__ __forceinline__ void mma8(float* d, const uint32_t* a, const uint32_t* b){
    asm volatile("mma.sync.aligned.m16n8k8.row.col.f32.tf32.tf32.f32 "
        "{%0,%1,%2,%3}, {%4,%5,%6,%7}, {%8,%9}, {%0,%1,%2,%3};"
        : "+f"(d[0]), "+f"(d[1]), "+f"(d[2]), "+f"(d[3])
        : "r"(a[0]), "r"(a[1]), "r"(a[2]), "r"(a[3]), "r"(b[0]), "r"(b[1]));
}
__device__ __forceinline__ float sigmoid_f(float x){
    return __fdividef(1.0f, 1.0f + __expf(-x));
}

// ============================================================================
// K1: fused LN(z) + h @ [Wp|Wg|Wgate] + p*sigmoid(g) epilogue.
// Weight cols reordered into 72 8-col tiles: tiles 0..63 interleave Wp/Wg
// (the p,g pair of one output column block sits in adjacent n-tiles of the
// same warp); tiles 64..71 = Wgate. a/b written channel-major for K2.
// ============================================================================
#define WPAD 68
#define N_COLS 576
#define K1_SMEM ((N_COLS*WPAD + 64*WPAD)*4)

__global__ void __launch_bounds__(512,1) k1_proj(
    const float* __restrict__ z, const float* __restrict__ lnw, const float* __restrict__ lnb,
    const float* __restrict__ Wp, const float* __restrict__ Wg, const float* __restrict__ Wgate)
{
    extern __shared__ float sm[];
    float* Wsm = sm;                   // [576][WPAD]  n-major, k contiguous
    float* Hsm = sm + N_COLS*WPAD;     // [64][WPAD]
    const int t = threadIdx.x;

    for (int idx = t; idx < N_COLS*D_IN; idx += 512){
        int k = idx / N_COLS, n = idx - k*N_COLS;
        int T = n >> 3, ct = n & 7;
        float v;
        if (T < 64){
            int col = (T>>1)*8 + ct;
            v = (T & 1) ? Wg[k*256 + col] : Wp[k*256 + col];
        } else {
            v = Wgate[k*64 + (T-64)*8 + ct];
        }
        Wsm[n*WPAD + k] = tf32f(v);
    }
    __syncthreads();

    const int lane = t & 31, w = t >> 5;
    const int wr = w >> 3, wc = w & 7;          // 2 warp-rows x 8 warp-cols
    const int grp = lane >> 2, tg = lane & 3;
    const int lr = t >> 3, lsub = t & 7;        // LN: 8 threads / row

    for (int tile = blockIdx.x; tile < (int)(R_TOT/64); tile += gridDim.x){
        const int row0 = tile * 64;
        // ---- fused LayerNorm of 64 rows into Hsm (tf32-rounded) ----
        {
            const float* zp = z + (size_t)(row0 + lr)*D_IN + lsub*8;
            float4 v0 = *(const float4*)zp;
            float4 v1 = *(const float4*)(zp + 4);
            float s = v0.x+v0.y+v0.z+v0.w + v1.x+v1.y+v1.z+v1.w;
            float q = v0.x*v0.x+v0.y*v0.y+v0.z*v0.z+v0.w*v0.w
                    + v1.x*v1.x+v1.y*v1.y+v1.z*v1.z+v1.w*v1.w;
            s += __shfl_xor_sync(0xffffffffu, s, 1); q += __shfl_xor_sync(0xffffffffu, q, 1);
            s += __shfl_xor_sync(0xffffffffu, s, 2); q += __shfl_xor_sync(0xffffffffu, q, 2);
            s += __shfl_xor_sync(0xffffffffu, s, 4); q += __shfl_xor_sync(0xffffffffu, q, 4);
            float mu = s * (1.0f/64.0f);
            float rstd = rsqrtf(q*(1.0f/64.0f) - mu*mu + LN_EPS);
            float* hp = Hsm + lr*WPAD + lsub*8;
            float e[8] = {v0.x,v0.y,v0.z,v0.w,v1.x,v1.y,v1.z,v1.w};
            #pragma unroll
            for (int x=0;x<8;x++)
                hp[x] = tf32f((e[x]-mu)*rstd*__ldg(lnw+lsub*8+x) + __ldg(lnb+lsub*8+x));
        }
        __syncthreads();

        float acc[9][2][4];
        #pragma unroll
        for (int a1=0;a1<9;a1++)
            #pragma unroll
            for (int a2=0;a2<2;a2++)
                #pragma unroll
                for (int a3=0;a3<4;a3++) acc[a1][a2][a3]=0.f;

        const int mbase = wr*32;
        #pragma unroll
        for (int kc=0; kc<8; kc++){
            const int kb = kc*8 + tg;
            uint32_t af[2][4];
            #pragma unroll
            for (int ms=0; ms<2; ms++){
                const float* p = Hsm + (mbase + ms*16 + grp)*WPAD + kb;
                af[ms][0] = __float_as_uint(p[0]);
                af[ms][1] = __float_as_uint(p[8*WPAD]);
                af[ms][2] = __float_as_uint(p[4]);
                af[ms][3] = __float_as_uint(p[8*WPAD+4]);
            }
            #pragma unroll
            for (int nt=0; nt<9; nt++){
                const int tileN = (nt<8) ? (wc*8+nt) : (64+wc);
                const float* p = Wsm + (tileN*8 + grp)*WPAD + kb;
                uint32_t bf[2] = {__float_as_uint(p[0]), __float_as_uint(p[4])};
                mma8(acc[nt][0], af[0], bf);
                mma8(acc[nt][1], af[1], bf);
            }
        }

        // ---- epilogue: pg = P*sig(G); split into a (c<128) / b ----
        #pragma unroll
        for (int pp=0; pp<4; pp++){
            const int colb = (wc*4+pp)*8 + tg*2;   // 0..255 over [a|b] channels
            #pragma unroll
            for (int ms=0; ms<2; ms++){
                #pragma unroll
                for (int e=0; e<4; e++){
                    float av = acc[2*pp][ms][e] * sigmoid_f(acc[2*pp+1][ms][e]);
                    int col = colb + (e&1);
                    int row = row0 + mbase + ms*16 + grp + ((e>>1)<<3);
                    float tv = tf32f(av);
                    if (col < D_HID) g_a[(size_t)col*R_TOT + row] = tv;
                    else             g_b[(size_t)(col-D_HID)*R_TOT + row] = tv;
                }
            }
        }
        #pragma unroll
        for (int ms=0; ms<2; ms++){
            #pragma unroll
            for (int e=0; e<4; e++){
                int col = wc*8 + tg*2 + (e&1);
                int row = row0 + mbase + ms*16 + grp + ((e>>1)<<3);
                g_gate[(size_t)row*D_IN + col] = sigmoid_f(acc[8][ms][e]);
            }
        }
        __syncthreads();
    }
}

// ============================================================================
// K2: per-channel NT GEMM  OP_c = A_c @ B_c^T   (128 channels x 512^3)
// ============================================================================
#define APAD 36
#define K2_STAGE (128*APAD)                 // floats per matrix per buffer
#define K2_SMEM (2*2*K2_STAGE*4)            // 73728 bytes

__device__ __forceinline__ void cp16(uint32_t s, const float* g){
    asm volatile("cp.async.cg.shared.global [%0], [%1], 16;"
                 :: "r"(s), "l"(__cvta_generic_to_global(g)) : "memory");
}
__device__ __forceinline__ void k2_prefetch(uint32_t smb, const float* Ag, const float* Bg,
                                            int t, int kt, int buf){
    const int kb = kt*32;
    #pragma unroll
    for (int s=0; s<4; s++){
        int gidx = t + s*256;
        int r = gidx >> 3, kp = (gidx & 7) << 2;
        cp16(smb + (uint32_t)((buf*2*K2_STAGE + r*APAD + kp)*4),
             Ag + (size_t)r*N_SEQ + kb + kp);
        cp16(smb + (uint32_t)((buf*2*K2_STAGE + K2_STAGE + r*APAD + kp)*4),
             Bg + (size_t)r*N_SEQ + kb + kp);
    }
    asm volatile("cp.async.commit_group;" ::: "memory");
}

__global__ void __launch_bounds__(256,2) k2_tri()
{
    extern __shared__ float sm[];
    const uint32_t smb = (uint32_t)__cvta_generic_to_shared(sm);
    const int c  = blockIdx.y;
    const int i0 = (blockIdx.x >> 2) * 128;
    const int j0 = (blockIdx.x & 3) * 128;
    const float* Ag = g_a + (size_t)c*R_TOT + (size_t)i0*N_SEQ;
    const float* Bg = g_b + (size_t)c*R_TOT + (size_t)j0*N_SEQ;

    const int t = threadIdx.x, lane = t & 31, w = t >> 5;
    const int grp = lane >> 2, tg = lane & 3;
    const int wm = (w >> 2) * 64, wn = (w & 3) * 32;

    float acc[4][4][4];
    #pragma unroll
    for (int a1=0;a1<4;a1++)
        #pragma unroll
        for (int a2=0;a2<4;a2++)
            #pragma unroll
            for (int a3=0;a3<4;a3++) acc[a1][a2][a3]=0.f;

    k2_prefetch(smb, Ag, Bg, t, 0, 0);

    for (int kt = 0; kt < 16; kt++){
        const int buf = kt & 1;
        if (kt < 15){
            k2_prefetch(smb, Ag, Bg, t, kt+1, buf^1);
            asm volatile("cp.async.wait_group 1;" ::: "memory");
        } else {
            asm volatile("cp.async.wait_group 0;" ::: "memory");
        }
        __syncthreads();

        const uint32_t* As = (const uint32_t*)(sm + buf*2*K2_STAGE);
        const uint32_t* Bs = As + K2_STAGE;
        #pragma unroll
        for (int kc=0; kc<4; kc++){
            const int kb = kc*8 + tg;
            uint32_t af[4][4];
            #pragma unroll
            for (int ms=0; ms<4; ms++){
                const uint32_t* p = As + (wm + ms*16 + grp)*APAD + kb;
                af[ms][0] = p[0];
                af[ms][1] = p[8*APAD];
                af[ms][2] = p[4];
                af[ms][3] = p[8*APAD+4];
            }
            #pragma unroll
            for (int ns=0; ns<4; ns++){
                const uint32_t* p = Bs + (wn + ns*8 + grp)*APAD + kb;
                uint32_t bf[2] = {p[0], p[4]};
                #pragma unroll
                for (int ms=0; ms<4; ms++) mma8(acc[ms][ns], af[ms], bf);
            }
        }
        __syncthreads();
    }

    // epilogue: g_op[c][i][j]
    #pragma unroll
    for (int ms=0; ms<4; ms++){
        #pragma unroll
        for (int ns=0; ns<4; ns++){
            size_t base = (size_t)c*R_TOT + (size_t)(i0+wm+ms*16+grp)*N_SEQ + (j0+wn+ns*8+tg*2);
            float2 v0 = {acc[ms][ns][0], acc[ms][ns][1]};
            float2 v1 = {acc[ms][ns][2], acc[ms][ns][3]};
            *(float2*)(g_op + base)            = v0;
            *(float2*)(g_op + base + 8*N_SEQ)  = v1;
        }
    }
}

// ============================================================================
// K3: transpose 128pos x 128chan tile, LN over channels, @Wout (tf32 mma),
//     * gate, write final output.
// ============================================================================
#define K3PAD 132
#define K3_SMEM ((128*K3PAD + 64*K3PAD)*4)   // 101376 bytes

__global__ void __launch_bounds__(256,2) k3_out(
    const float* __restrict__ lnow, const float* __restrict__ lnob,
    const float* __restrict__ Wout, float* __restrict__ outp)
{
    extern __shared__ float sm[];
    float* Op = sm;                   // [128 pos][K3PAD] channels contiguous
    float* Wsm = sm + 128*K3PAD;      // [64 n][K3PAD] k contiguous
    const int t = threadIdx.x;
    const int pos0 = blockIdx.x * 128;

    // load Wout transposed (n-major)
    for (int idx = t; idx < 64*128; idx += 256){
        int k = idx >> 6, n = idx & 63;
        Wsm[n*K3PAD + k] = tf32f(Wout[k*64 + n]);
    }
    // load op tile: coalesced over positions per channel row
    for (int idx = t; idx < 128*128; idx += 256){
        int c = idx >> 7, p = idx & 127;
        Op[p*K3PAD + c] = g_op[(size_t)c*R_TOT + pos0 + p];
    }
    __syncthreads();

    // LN over 128 channels: 2 threads per position
    {
        const int r = t >> 1, h = t & 1;
        float* base = Op + r*K3PAD + h*64;
        float s = 0.f, q = 0.f;
        #pragma unroll
        for (int j=0; j<16; j++){
            float4 v = *(float4*)(base + j*4);
            s += v.x+v.y+v.z+v.w;
            q += v.x*v.x+v.y*v.y+v.z*v.z+v.w*v.w;
        }
        s += __shfl_xor_sync(0xffffffffu, s, 1);
        q += __shfl_xor_sync(0xffffffffu, q, 1);
        float mu = s * (1.0f/128.0f);
        float rstd = rsqrtf(q*(1.0f/128.0f) - mu*mu + LN_EPS);
        #pragma unroll
        for (int j=0; j<16; j++){
            float4 v = *(float4*)(base + j*4);
            int cb = h*64 + j*4;
            v.x = tf32f((v.x-mu)*rstd*__ldg(lnow+cb+0) + __ldg(lnob+cb+0));
            v.y = tf32f((v.y-mu)*rstd*__ldg(lnow+cb+1) + __ldg(lnob+cb+1));
            v.z = tf32f((v.z-mu)*rstd*__ldg(lnow+cb+2) + __ldg(lnob+cb+2));
            v.w = tf32f((v.w-mu)*rstd*__ldg(lnow+cb+3) + __ldg(lnob+cb+3));
            *(float4*)(base + j*4) = v;
        }
    }
    __syncthreads();

    // mma: M=128 (8 warps x 16), N=64, K=128
    const int lane = t & 31, w = t >> 5;
    const int grp = lane >> 2, tg = lane & 3;
    float acc[8][4];
    #pragma unroll
    for (int a1=0;a1<8;a1++)
        #pragma unroll
        for (int a3=0;a3<4;a3++) acc[a1][a3]=0.f;

    #pragma unroll
    for (int kc=0; kc<16; kc++){
        const int kb = kc*8 + tg;
        const float* pa = Op + (w*16 + grp)*K3PAD + kb;
        uint32_t af[4] = {
            __float_as_uint(pa[0]),
            __float_as_uint(pa[8*K3PAD]),
            __float_as_uint(pa[4]),
            __float_as_uint(pa[8*K3PAD+4])
        };
        #pragma unroll
        for (int nt=0; nt<8; nt++){
            const float* pb = Wsm + (nt*8 + grp)*K3PAD + kb;
            uint32_t bf[2] = {__float_as_uint(pb[0]), __float_as_uint(pb[4])};
            mma8(acc[nt], af, bf);
        }
    }

    // epilogue: * gate, write out
    #pragma unroll
    for (int nt=0; nt<8; nt++){
        const int colb = nt*8 + tg*2;
        const int r0 = pos0 + w*16 + grp;
        float2 gv0 = *(const float2*)(g_gate + (size_t)r0*D_IN + colb);
        float2 gv1 = *(const float2*)(g_gate + (size_t)(r0+8)*D_IN + colb);
        float2 o0 = {acc[nt][0]*gv0.x, acc[nt][1]*gv0.y};
        float2 o1 = {acc[nt][2]*gv1.x, acc[nt][3]*gv1.y};
        *(float2*)(outp + (size_t)r0*D_IN + colb)     = o0;
        *(float2*)(outp + (size_t)(r0+8)*D_IN + colb) = o1;
    }
}

// ============================================================================
extern "C" void kernel_launch(void* const* d_in, const int* in_sizes, int n_in,
                              void* d_out, int out_size) {
    (void)in_sizes; (void)n_in; (void)out_size;
    const float* z     = (const float*)d_in[0];
    const float* lniw  = (const float*)d_in[1];
    const float* lnib  = (const float*)d_in[2];
    const float* Wp    = (const float*)d_in[3];
    const float* Wg    = (const float*)d_in[4];
    const float* lnow  = (const float*)d_in[5];
    const float* lnob  = (const float*)d_in[6];
    const float* Wout  = (const float*)d_in[7];
    const float* Wgate = (const float*)d_in[8];
    float* outp = (float*)d_out;

    cudaFuncSetAttribute(k1_proj, cudaFuncAttributeMaxDynamicSharedMemorySize, K1_SMEM);
    cudaFuncSetAttribute(k2_tri,  cudaFuncAttributeMaxDynamicSharedMemorySize, K2_SMEM);
    cudaFuncSetAttribute(k3_out,  cudaFuncAttributeMaxDynamicSharedMemorySize, K3_SMEM);

    k1_proj<<<148, 512, K1_SMEM>>>(z, lniw, lnib, Wp, Wg, Wgate);
    k2_tri<<<dim3(16,128,1), 256, K2_SMEM>>>();
    k3_out<<<2048, 256, K3_SMEM>>>(lnow, lnob, Wout, outp);
}

// round 5
// speedup vs baseline: 1.0205x; 1.0205x over previous
#include <cuda_runtime.h>
#include <cuda_bf16.h>
#include <cstdint>

#define N_SEQ 512
#define D_IN 64
#define D_HID 128
#define LN_EPS 1e-5f
constexpr size_t R_TOT = (size_t)N_SEQ * N_SEQ;   // 262144

// ---------------- scratch (static device globals — allocation-free) ----------
__device__ float g_a[(size_t)D_HID * R_TOT];     // [c][i*N+k]  tf32-rounded
__device__ float g_b[(size_t)D_HID * R_TOT];     // [c][j*N+k]  tf32-rounded
__device__ float g_gate[R_TOT * D_IN];           // [row][64]   post-sigmoid fp32
__device__ float g_op[(size_t)D_HID * R_TOT];    // [c][i*N+j]  fp32

// ---------------- helpers ----------------------------------------------------
__device__ __forceinline__ float tf32f(float x){
    uint32_t u = __float_as_uint(x);
    asm("cvt.rna.tf32.f32 %0, %0;" : "+r"(u));
    return __uint_as_float(u);
}
__device__ __forceinline__ void mma8(float* d, const uint32_t* a, const uint32_t* b){
    asm volatile("mma.sync.aligned.m16n8k8.row.col.f32.tf32.tf32.f32 "
        "{%0,%1,%2,%3}, {%4,%5,%6,%7}, {%8,%9}, {%0,%1,%2,%3};"
        : "+f"(d[0]), "+f"(d[1]), "+f"(d[2]), "+f"(d[3])
        : "r"(a[0]), "r"(a[1]), "r"(a[2]), "r"(a[3]), "r"(b[0]), "r"(b[1]));
}
__device__ __forceinline__ float sigmoid_f(float x){
    return __fdividef(1.0f, 1.0f + __expf(-x));
}
__device__ __forceinline__ void cp16(uint32_t s, const float* g){
    asm volatile("cp.async.cg.shared.global [%0], [%1], 16;"
                 :: "r"(s), "l"(__cvta_generic_to_global(g)) : "memory");
}

// ============================================================================
// K1: fused LN(z) + h @ [Wp|Wg|Wgate] + p*sigmoid(g).
// z prefetched one tile ahead via cp.async into double-buffered Hsm;
// LN computed in place; single __syncthreads per tile.
// ============================================================================
#define WPAD 68
#define N_COLS 576
#define K1_SMEM ((N_COLS*WPAD + 2*64*WPAD)*4)   // 191488

__device__ __forceinline__ void k1_load_z(uint32_t smb_h, const float* z, int tile, int buf, int t){
    const int lr = t >> 3, lsub = t & 7;
    uint32_t dst = smb_h + (uint32_t)((buf*64*WPAD + lr*WPAD + lsub*8)*4);
    const float* src = z + (size_t)(tile*64 + lr)*D_IN + lsub*8;
    cp16(dst, src);
    cp16(dst + 16, src + 4);
    asm volatile("cp.async.commit_group;" ::: "memory");
}

__global__ void __launch_bounds__(512,1) k1_proj(
    const float* __restrict__ z, const float* __restrict__ lnw, const float* __restrict__ lnb,
    const float* __restrict__ Wp, const float* __restrict__ Wg, const float* __restrict__ Wgate)
{
    extern __shared__ float sm[];
    float* Wsm = sm;                   // [576][WPAD]  n-major, k contiguous
    float* Hsm = sm + N_COLS*WPAD;     // 2 x [64][WPAD]
    const uint32_t smb_h = (uint32_t)__cvta_generic_to_shared(Hsm);
    const int t = threadIdx.x;
    const int NT = (int)(R_TOT/64);

    for (int idx = t; idx < N_COLS*D_IN; idx += 512){
        int k = idx / N_COLS, n = idx - k*N_COLS;
        int T = n >> 3, ct = n & 7;
        float v;
        if (T < 64){
            int col = (T>>1)*8 + ct;
            v = (T & 1) ? Wg[k*256 + col] : Wp[k*256 + col];
        } else {
            v = Wgate[k*64 + (T-64)*8 + ct];
        }
        Wsm[n*WPAD + k] = tf32f(v);
    }

    const int lane = t & 31, w = t >> 5;
    const int wr = w >> 3, wc = w & 7;          // 2 warp-rows x 8 warp-cols
    const int grp = lane >> 2, tg = lane & 3;
    const int lr = t >> 3, lsub = t & 7;        // LN: 8 threads / row
    const float lw0 = __ldg(lnw+lsub*8+0), lw1 = __ldg(lnw+lsub*8+1),
                lw2 = __ldg(lnw+lsub*8+2), lw3 = __ldg(lnw+lsub*8+3),
                lw4 = __ldg(lnw+lsub*8+4), lw5 = __ldg(lnw+lsub*8+5),
                lw6 = __ldg(lnw+lsub*8+6), lw7 = __ldg(lnw+lsub*8+7);
    const float lb0 = __ldg(lnb+lsub*8+0), lb1 = __ldg(lnb+lsub*8+1),
                lb2 = __ldg(lnb+lsub*8+2), lb3 = __ldg(lnb+lsub*8+3),
                lb4 = __ldg(lnb+lsub*8+4), lb5 = __ldg(lnb+lsub*8+5),
                lb6 = __ldg(lnb+lsub*8+6), lb7 = __ldg(lnb+lsub*8+7);

    int buf = 0;
    if ((int)blockIdx.x < NT) k1_load_z(smb_h, z, blockIdx.x, 0, t);

    for (int tile = blockIdx.x; tile < NT; tile += gridDim.x, buf ^= 1){
        const int row0 = tile * 64;
        asm volatile("cp.async.wait_group 0;" ::: "memory");

        // ---- in-place LayerNorm of own 8 elements ----
        {
            float* hp = Hsm + buf*64*WPAD + lr*WPAD + lsub*8;
            float4 v0 = *(float4*)hp;
            float4 v1 = *(float4*)(hp + 4);
            float s = v0.x+v0.y+v0.z+v0.w + v1.x+v1.y+v1.z+v1.w;
            float q = v0.x*v0.x+v0.y*v0.y+v0.z*v0.z+v0.w*v0.w
                    + v1.x*v1.x+v1.y*v1.y+v1.z*v1.z+v1.w*v1.w;
            s += __shfl_xor_sync(0xffffffffu, s, 1); q += __shfl_xor_sync(0xffffffffu, q, 1);
            s += __shfl_xor_sync(0xffffffffu, s, 2); q += __shfl_xor_sync(0xffffffffu, q, 2);
            s += __shfl_xor_sync(0xffffffffu, s, 4); q += __shfl_xor_sync(0xffffffffu, q, 4);
            float mu = s * (1.0f/64.0f);
            float rstd = rsqrtf(q*(1.0f/64.0f) - mu*mu + LN_EPS);
            hp[0] = tf32f((v0.x-mu)*rstd*lw0 + lb0);
            hp[1] = tf32f((v0.y-mu)*rstd*lw1 + lb1);
            hp[2] = tf32f((v0.z-mu)*rstd*lw2 + lb2);
            hp[3] = tf32f((v0.w-mu)*rstd*lw3 + lb3);
            hp[4] = tf32f((v1.x-mu)*rstd*lw4 + lb4);
            hp[5] = tf32f((v1.y-mu)*rstd*lw5 + lb5);
            hp[6] = tf32f((v1.z-mu)*rstd*lw6 + lb6);
            hp[7] = tf32f((v1.w-mu)*rstd*lw7 + lb7);
        }
        __syncthreads();

        // prefetch next tile while mma runs
        int ntile = tile + gridDim.x;
        if (ntile < NT) k1_load_z(smb_h, z, ntile, buf^1, t);

        float acc[9][2][4];
        #pragma unroll
        for (int a1=0;a1<9;a1++)
            #pragma unroll
            for (int a2=0;a2<2;a2++)
                #pragma unroll
                for (int a3=0;a3<4;a3++) acc[a1][a2][a3]=0.f;

        const int mbase = wr*32;
        const float* Hb = Hsm + buf*64*WPAD;
        #pragma unroll
        for (int kc=0; kc<8; kc++){
            const int kb = kc*8 + tg;
            uint32_t af[2][4];
            #pragma unroll
            for (int ms=0; ms<2; ms++){
                const float* p = Hb + (mbase + ms*16 + grp)*WPAD + kb;
                af[ms][0] = __float_as_uint(p[0]);
                af[ms][1] = __float_as_uint(p[8*WPAD]);
                af[ms][2] = __float_as_uint(p[4]);
                af[ms][3] = __float_as_uint(p[8*WPAD+4]);
            }
            #pragma unroll
            for (int nt=0; nt<9; nt++){
                const int tileN = (nt<8) ? (wc*8+nt) : (64+wc);
                const float* p = Wsm + (tileN*8 + grp)*WPAD + kb;
                uint32_t bf[2] = {__float_as_uint(p[0]), __float_as_uint(p[4])};
                mma8(acc[nt][0], af[0], bf);
                mma8(acc[nt][1], af[1], bf);
            }
        }

        // ---- epilogue: pg = P*sig(G); split into a (c<128) / b ----
        #pragma unroll
        for (int pp=0; pp<4; pp++){
            const int colb = (wc*4+pp)*8 + tg*2;
            #pragma unroll
            for (int ms=0; ms<2; ms++){
                #pragma unroll
                for (int e=0; e<4; e++){
                    float av = acc[2*pp][ms][e] * sigmoid_f(acc[2*pp+1][ms][e]);
                    int col = colb + (e&1);
                    int row = row0 + mbase + ms*16 + grp + ((e>>1)<<3);
                    float tv = tf32f(av);
                    if (col < D_HID) g_a[(size_t)col*R_TOT + row] = tv;
                    else             g_b[(size_t)(col-D_HID)*R_TOT + row] = tv;
                }
            }
        }
        #pragma unroll
        for (int ms=0; ms<2; ms++){
            #pragma unroll
            for (int e=0; e<4; e++){
                int col = wc*8 + tg*2 + (e&1);
                int row = row0 + mbase + ms*16 + grp + ((e>>1)<<3);
                g_gate[(size_t)row*D_IN + col] = sigmoid_f(acc[8][ms][e]);
            }
        }
    }
}

// ============================================================================
// K2: per-channel NT GEMM OP_c = A_c @ B_c^T (128 channels x 512^3), legacy
// tf32 mma.sync. 128x128x32 stages, double-buffered cp.async, ONE sync/stage.
// Fragment loads are LDS.128 via consistent k-slot permutation:
//   hardware slot (g2, gi, tg/tg+4)  <->  logical k = 16*g2 + 4*tg + {0..3}
// Row stride 48 floats (== 16 mod 32 banks) -> conflict-free float4 loads.
// ============================================================================
#define K2_STRIDE 48
#define K2_MAT (128*K2_STRIDE)              // 6144 floats (24576 B)
#define K2_STAGE2 (2*K2_MAT)                // A + B
#define K2_SMEM (2*K2_STAGE2*4)             // 98304 B

__device__ __forceinline__ void k2_load(uint32_t smb, const float* Ag, const float* Bg,
                                        int t, int kt, int buf){
    const int kb = kt*32;
    const uint32_t base = smb + (uint32_t)(buf*K2_STAGE2*4);
    #pragma unroll
    for (int s=0; s<4; s++){
        int idx = t + s*256;                 // 0..1023
        int r = idx >> 3, ci = idx & 7;
        uint32_t off = (uint32_t)(r*(K2_STRIDE*4) + ci*16);
        cp16(base + off,                    Ag + (size_t)r*N_SEQ + kb + ci*4);
        cp16(base + (uint32_t)(K2_MAT*4) + off, Bg + (size_t)r*N_SEQ + kb + ci*4);
    }
    asm volatile("cp.async.commit_group;" ::: "memory");
}

__global__ void __launch_bounds__(256,2) k2_tri()
{
    extern __shared__ float sm[];
    const uint32_t smb = (uint32_t)__cvta_generic_to_shared(sm);
    const int c  = blockIdx.y;
    const int i0 = (blockIdx.x >> 2) * 128;
    const int j0 = (blockIdx.x & 3) * 128;
    const float* Ag = g_a + (size_t)c*R_TOT + (size_t)i0*N_SEQ;
    const float* Bg = g_b + (size_t)c*R_TOT + (size_t)j0*N_SEQ;

    const int t = threadIdx.x, lane = t & 31, w = t >> 5;
    const int grp = lane >> 2, tg = lane & 3;
    const int wm = (w >> 2) * 64, wn = (w & 3) * 32;

    float acc[4][4][4];
    #pragma unroll
    for (int a1=0;a1<4;a1++)
        #pragma unroll
        for (int a2=0;a2<4;a2++)
            #pragma unroll
            for (int a3=0;a3<4;a3++) acc[a1][a2][a3]=0.f;

    k2_load(smb, Ag, Bg, t, 0, 0);

    for (int kt = 0; kt < 16; kt++){
        const int buf = kt & 1;
        asm volatile("cp.async.wait_group 0;" ::: "memory");
        __syncthreads();
        if (kt < 15) k2_load(smb, Ag, Bg, t, kt+1, buf^1);

        const float* As = sm + buf*K2_STAGE2;
        const float* Bs = As + K2_MAT;
        #pragma unroll
        for (int g2=0; g2<2; g2++){
            float4 av[4][2];
            #pragma unroll
            for (int ms=0; ms<4; ms++){
                const float* p = As + (wm + ms*16 + grp)*K2_STRIDE + g2*16 + tg*4;
                av[ms][0] = *(const float4*)p;
                av[ms][1] = *(const float4*)(p + 8*K2_STRIDE);
            }
            float4 bv[4];
            #pragma unroll
            for (int ns=0; ns<4; ns++){
                const float* p = Bs + (wn + ns*8 + grp)*K2_STRIDE + g2*16 + tg*4;
                bv[ns] = *(const float4*)p;
            }
            // gi = 0: components .x (slot tg) / .y (slot tg+4)
            #pragma unroll
            for (int ns=0; ns<4; ns++){
                uint32_t bf[2] = {__float_as_uint(bv[ns].x), __float_as_uint(bv[ns].y)};
                #pragma unroll
                for (int ms=0; ms<4; ms++){
                    uint32_t af[4] = {__float_as_uint(av[ms][0].x), __float_as_uint(av[ms][1].x),
                                      __float_as_uint(av[ms][0].y), __float_as_uint(av[ms][1].y)};
                    mma8(acc[ms][ns], af, bf);
                }
            }
            // gi = 1: components .z / .w
            #pragma unroll
            for (int ns=0; ns<4; ns++){
                uint32_t bf[2] = {__float_as_uint(bv[ns].z), __float_as_uint(bv[ns].w)};
                #pragma unroll
                for (int ms=0; ms<4; ms++){
                    uint32_t af[4] = {__float_as_uint(av[ms][0].z), __float_as_uint(av[ms][1].z),
                                      __float_as_uint(av[ms][0].w), __float_as_uint(av[ms][1].w)};
                    mma8(acc[ms][ns], af, bf);
                }
            }
        }
    }

    // epilogue: g_op[c][i][j]
    #pragma unroll
    for (int ms=0; ms<4; ms++){
        #pragma unroll
        for (int ns=0; ns<4; ns++){
            size_t base = (size_t)c*R_TOT + (size_t)(i0+wm+ms*16+grp)*N_SEQ + (j0+wn+ns*8+tg*2);
            float2 v0 = {acc[ms][ns][0], acc[ms][ns][1]};
            float2 v1 = {acc[ms][ns][2], acc[ms][ns][3]};
            *(float2*)(g_op + base)            = v0;
            *(float2*)(g_op + base + 8*N_SEQ)  = v1;
        }
    }
}

// ============================================================================
// K3: transpose 128pos x 128chan tile, LN over channels, @Wout (tf32 mma),
//     * gate, write final output.
// ============================================================================
#define K3PAD 132
#define K3_SMEM ((128*K3PAD + 64*K3PAD)*4)   // 101376

__global__ void __launch_bounds__(256,2) k3_out(
    const float* __restrict__ lnow, const float* __restrict__ lnob,
    const float* __restrict__ Wout, float* __restrict__ outp)
{
    extern __shared__ float sm[];
    float* Op = sm;                   // [128 pos][K3PAD] channels contiguous
    float* Wsm = sm + 128*K3PAD;      // [64 n][K3PAD] k contiguous
    const int t = threadIdx.x;
    const int pos0 = blockIdx.x * 128;

    for (int idx = t; idx < 64*128; idx += 256){
        int k = idx >> 6, n = idx & 63;
        Wsm[n*K3PAD + k] = tf32f(Wout[k*64 + n]);
    }
    for (int idx = t; idx < 128*128; idx += 256){
        int c = idx >> 7, p = idx & 127;
        Op[p*K3PAD + c] = g_op[(size_t)c*R_TOT + pos0 + p];
    }
    __syncthreads();

    {
        const int r = t >> 1, h = t & 1;
        float* base = Op + r*K3PAD + h*64;
        float s = 0.f, q = 0.f;
        #pragma unroll
        for (int j=0; j<16; j++){
            float4 v = *(float4*)(base + j*4);
            s += v.x+v.y+v.z+v.w;
            q += v.x*v.x+v.y*v.y+v.z*v.z+v.w*v.w;
        }
        s += __shfl_xor_sync(0xffffffffu, s, 1);
        q += __shfl_xor_sync(0xffffffffu, q, 1);
        float mu = s * (1.0f/128.0f);
        float rstd = rsqrtf(q*(1.0f/128.0f) - mu*mu + LN_EPS);
        #pragma unroll
        for (int j=0; j<16; j++){
            float4 v = *(float4*)(base + j*4);
            int cb = h*64 + j*4;
            v.x = tf32f((v.x-mu)*rstd*__ldg(lnow+cb+0) + __ldg(lnob+cb+0));
            v.y = tf32f((v.y-mu)*rstd*__ldg(lnow+cb+1) + __ldg(lnob+cb+1));
            v.z = tf32f((v.z-mu)*rstd*__ldg(lnow+cb+2) + __ldg(lnob+cb+2));
            v.w = tf32f((v.w-mu)*rstd*__ldg(lnow+cb+3) + __ldg(lnob+cb+3));
            *(float4*)(base + j*4) = v;
        }
    }
    __syncthreads();

    const int lane = t & 31, w = t >> 5;
    const int grp = lane >> 2, tg = lane & 3;
    float acc[8][4];
    #pragma unroll
    for (int a1=0;a1<8;a1++)
        #pragma unroll
        for (int a3=0;a3<4;a3++) acc[a1][a3]=0.f;

    #pragma unroll
    for (int kc=0; kc<16; kc++){
        const int kb = kc*8 + tg;
        const float* pa = Op + (w*16 + grp)*K3PAD + kb;
        uint32_t af[4] = {
            __float_as_uint(pa[0]),
            __float_as_uint(pa[8*K3PAD]),
            __float_as_uint(pa[4]),
            __float_as_uint(pa[8*K3PAD+4])
        };
        #pragma unroll
        for (int nt=0; nt<8; nt++){
            const float* pb = Wsm + (nt*8 + grp)*K3PAD + kb;
            uint32_t bf[2] = {__float_as_uint(pb[0]), __float_as_uint(pb[4])};
            mma8(acc[nt], af, bf);
        }
    }

    #pragma unroll
    for (int nt=0; nt<8; nt++){
        const int colb = nt*8 + tg*2;
        const int r0 = pos0 + w*16 + grp;
        float2 gv0 = *(const float2*)(g_gate + (size_t)r0*D_IN + colb);
        float2 gv1 = *(const float2*)(g_gate + (size_t)(r0+8)*D_IN + colb);
        float2 o0 = {acc[nt][0]*gv0.x, acc[nt][1]*gv0.y};
        float2 o1 = {acc[nt][2]*gv1.x, acc[nt][3]*gv1.y};
        *(float2*)(outp + (size_t)r0*D_IN + colb)     = o0;
        *(float2*)(outp + (size_t)(r0+8)*D_IN + colb) = o1;
    }
}

// ============================================================================
extern "C" void kernel_launch(void* const* d_in, const int* in_sizes, int n_in,
                              void* d_out, int out_size) {
    (void)in_sizes; (void)n_in; (void)out_size;
    const float* z     = (const float*)d_in[0];
    const float* lniw  = (const float*)d_in[1];
    const float* lnib  = (const float*)d_in[2];
    const float* Wp    = (const float*)d_in[3];
    const float* Wg    = (const float*)d_in[4];
    const float* lnow  = (const float*)d_in[5];
    const float* lnob  = (const float*)d_in[6];
    const float* Wout  = (const float*)d_in[7];
    const float* Wgate = (const float*)d_in[8];
    float* outp = (float*)d_out;

    cudaFuncSetAttribute(k1_proj, cudaFuncAttributeMaxDynamicSharedMemorySize, K1_SMEM);
    cudaFuncSetAttribute(k2_tri,  cudaFuncAttributeMaxDynamicSharedMemorySize, K2_SMEM);
    cudaFuncSetAttribute(k3_out,  cudaFuncAttributeMaxDynamicSharedMemorySize, K3_SMEM);

    k1_proj<<<148, 512, K1_SMEM>>>(z, lniw, lnib, Wp, Wg, Wgate);
    k2_tri<<<dim3(16,128,1), 256, K2_SMEM>>>();
    k3_out<<<2048, 256, K3_SMEM>>>(lnow, lnob, Wout, outp);
}